// round 1
// baseline (speedup 1.0000x reference)
#include <cuda_runtime.h>
#include <stdint.h>

// Scratch (allocation-free rule: __device__ globals)
#define MAXN 131072
__device__ int g_counts[MAXN];
__device__ int g_lastidx[MAXN];

// ---------------------------------------------------------------------------
// Kernel 1: zero sum region of d_out + scratch arrays
// ---------------------------------------------------------------------------
__global__ void init_kernel(float4* __restrict__ sums4, int n_vec4, int n_nodes) {
    int i = blockIdx.x * blockDim.x + threadIdx.x;
    int stride = gridDim.x * blockDim.x;
    float4 z = make_float4(0.f, 0.f, 0.f, 0.f);
    for (int j = i; j < n_vec4; j += stride) sums4[j] = z;
    for (int j = i; j < n_nodes; j += stride) {
        g_counts[j] = 0;
        g_lastidx[j] = 0;
    }
}

// ---------------------------------------------------------------------------
// Kernel 2: scatter-add. One warp per message row (D=256 f32 = 64 float4).
// Each lane: 2 coalesced float4 loads + 2 red.global.add.v4.f32.
// ---------------------------------------------------------------------------
__global__ void scatter_kernel(const int* __restrict__ node_ids,
                               const float4* __restrict__ messages,
                               float* __restrict__ sums,
                               int B) {
    int gwarp = (blockIdx.x * blockDim.x + threadIdx.x) >> 5;
    int lane = threadIdx.x & 31;
    if (gwarp >= B) return;

    int node = __ldg(&node_ids[gwarp]);
    const float4* row = messages + (size_t)gwarp * 64;
    float4 a = row[lane];        // bytes [lane*16 .. ) first 512B
    float4 b = row[lane + 32];   // second 512B

    float* dst = sums + (size_t)node * 256;
    asm volatile("red.global.add.v4.f32 [%0], {%1,%2,%3,%4};"
                 :: "l"(dst + lane * 4),
                    "f"(a.x), "f"(a.y), "f"(a.z), "f"(a.w) : "memory");
    asm volatile("red.global.add.v4.f32 [%0], {%1,%2,%3,%4};"
                 :: "l"(dst + lane * 4 + 128),
                    "f"(b.x), "f"(b.y), "f"(b.z), "f"(b.w) : "memory");

    if (lane == 0) {
        atomicAdd(&g_counts[node], 1);
        atomicMax(&g_lastidx[node], gwarp);  // timestamps index-ordered
    }
}

// ---------------------------------------------------------------------------
// Kernel 3: finalize. One block (64 threads) per node: scale row by 1/count,
// emit last_timestamp and count.
// ---------------------------------------------------------------------------
__global__ void finalize_kernel(float* __restrict__ out_mean,
                                float* __restrict__ out_ts,
                                float* __restrict__ out_cnt,
                                const float* __restrict__ timestamps,
                                int n_nodes) {
    int n = blockIdx.x;
    if (n >= n_nodes) return;
    int c = g_counts[n];
    float inv = 1.0f / (float)(c > 0 ? c : 1);

    float4* row = reinterpret_cast<float4*>(out_mean + (size_t)n * 256);
    int t = threadIdx.x;  // 64 threads, one float4 each
    float4 v = row[t];
    v.x *= inv; v.y *= inv; v.z *= inv; v.w *= inv;
    row[t] = v;

    if (t == 0) {
        out_ts[n]  = (c > 0) ? __ldg(&timestamps[g_lastidx[n]]) : 0.0f;
        out_cnt[n] = (float)c;
    }
}

// ---------------------------------------------------------------------------
// Launch. Inputs (metadata order): node_ids[B] i32, messages[B*D] f32,
// timestamps[B] f32, n_nodes scalar i32 (ignored; derived from out_size).
// Output: [N*D mean | N last_ts | N counts] float32.
// ---------------------------------------------------------------------------
extern "C" void kernel_launch(void* const* d_in, const int* in_sizes, int n_in,
                              void* d_out, int out_size) {
    const int*   node_ids   = (const int*)d_in[0];
    const float* messages   = (const float*)d_in[1];
    const float* timestamps = (const float*)d_in[2];

    int B = in_sizes[0];
    int D = in_sizes[1] / B;          // expected 256
    int N = out_size / (D + 2);       // N*(D+2) total output elements

    float* out_mean = (float*)d_out;
    float* out_ts   = out_mean + (size_t)N * D;
    float* out_cnt  = out_ts + N;

    // 1) init: zero N*D floats (as float4) + scratch
    {
        int n_vec4 = (N * D) / 4;
        int threads = 256;
        int blocks = 2048;
        init_kernel<<<blocks, threads>>>((float4*)out_mean, n_vec4, N);
    }

    // 2) scatter: one warp per message
    {
        int threads = 256;                       // 8 warps/block
        int blocks = (B + 7) / 8;
        scatter_kernel<<<blocks, threads>>>(node_ids, (const float4*)messages,
                                            out_mean, B);
    }

    // 3) finalize: one block per node
    {
        finalize_kernel<<<N, 64>>>(out_mean, out_ts, out_cnt, timestamps, N);
    }
}